// round 1
// baseline (speedup 1.0000x reference)
#include <cuda_runtime.h>
#include <cuda_bf16.h>

// out[b,c,h,w] = x[b,0,h,w] + 2*sum_{k=1..C-1} x[b,k,h,w]*cos(pi*k*(c+0.5)/C)
// (DCT-III along channels; derived exactly from the reference ifft construction)
//
// Parity trick: M[C-1-c][k] = (-1)^k M[c][k]
//   E[c] = sum_{k even} M[c][k] x[k],  O[c] = sum_{k odd} M[c][k] x[k]
//   out[c] = E+O, out[C-1-c] = E-O   for c in [0, C/2)

#define C_DIM 256
#define HALF  128
#define HW    16384   // 128*128
#define BM    64      // c-half values per block
#define BN    128     // pixels per block
#define BK    16

// Precomputed matrix, even/odd k reordered, each value duplicated along columns:
// row kp in [0,128): k = 2*kp (even phase); kp in [128,256): k = 2*(kp-128)+1 (odd)
// col 2c and 2c+1 both hold M[c][k], c in [0,128)
__device__ float g_Adup[256 * 256];

__global__ void precompute_kernel() {
    int idx = blockIdx.x * blockDim.x + threadIdx.x;   // 0..32767
    if (idx >= 256 * 128) return;
    int kp = idx >> 7;      // 0..255
    int c  = idx & 127;     // 0..127
    int k  = (kp < 128) ? (2 * kp) : (2 * (kp - 128) + 1);
    float val;
    if (k == 0) {
        val = 1.0f;
    } else {
        // M = 2*cos(pi * k*(2c+1) / 512); reduce k*(2c+1) mod 1024 exactly in int
        int m = (k * (2 * c + 1)) & 1023;
        val = 2.0f * cospif((float)m * (1.0f / 512.0f));
    }
    g_Adup[kp * 256 + 2 * c]     = val;
    g_Adup[kp * 256 + 2 * c + 1] = val;
}

#define FMA2(d, a, b) \
    asm("fma.rn.f32x2 %0, %1, %2, %0;" : "+l"(d) : "l"(a), "l"(b))

#define ULO(u) __uint_as_float((unsigned)(u))
#define UHI(u) __uint_as_float((unsigned)((u) >> 32))

__global__ __launch_bounds__(256, 2)
void idct_gemm_kernel(const float* __restrict__ x, float* __restrict__ out) {
    __shared__ __align__(16) float As[BK][2 * BM];  // 16 x 128 (duplicated c cols)
    __shared__ __align__(16) float Bs[BK][BN];      // 16 x 128 pixels

    const int tid   = threadIdx.x;
    const int ctile = blockIdx.x;    // 0..1  (which 64-wide c-half tile)
    const int ptile = blockIdx.y;    // 0..127
    const int batch = blockIdx.z;

    const float* xb = x   + (size_t)batch * C_DIM * HW + (size_t)ptile * BN;
    float*       ob = out + (size_t)batch * C_DIM * HW + (size_t)ptile * BN;

    const int tx = tid & 15;   // pixel group
    const int ty = tid >> 4;   // c group

    // global->smem load mapping: 512 float4 per tile, 2 per thread
    const int ar0 = tid >> 5;          // row 0..7 (second load: +8)
    const int ac0 = (tid & 31) * 4;    // float col 0..124

    unsigned long long accE[4][4];
    unsigned long long accO[4][4];
#pragma unroll
    for (int i = 0; i < 4; i++)
#pragma unroll
        for (int j = 0; j < 4; j++) { accE[i][j] = 0ULL; accO[i][j] = 0ULL; }

#pragma unroll 1
    for (int phase = 0; phase < 2; ++phase) {
#pragma unroll 1
        for (int kt = 0; kt < HALF / BK; ++kt) {
            // A tile: rows kp = phase*128 + kt*16 + r, duplicated cols [ctile*128, +128)
            const float* Ag = g_Adup + (size_t)(phase * 128 + kt * 16) * 256 + ctile * 128;
            *(float4*)&As[ar0][ac0]     = *(const float4*)&Ag[(size_t)ar0 * 256 + ac0];
            *(float4*)&As[ar0 + 8][ac0] = *(const float4*)&Ag[(size_t)(ar0 + 8) * 256 + ac0];
            // B tile: x rows k = 2*(kt*16 + r) + phase
            const float* Bg = xb + (size_t)(2 * (kt * 16) + phase) * HW;
            *(float4*)&Bs[ar0][ac0]     = *(const float4*)&Bg[(size_t)(2 * ar0) * HW + ac0];
            *(float4*)&Bs[ar0 + 8][ac0] = *(const float4*)&Bg[(size_t)(2 * (ar0 + 8)) * HW + ac0];
            __syncthreads();

            unsigned long long(*acc)[4] = phase ? accO : accE;
#pragma unroll
            for (int kk = 0; kk < BK; ++kk) {
                // a: 4 c-values, pre-duplicated pairs (a,a)
                ulonglong2 a01 = *(const ulonglong2*)&As[kk][ty * 8];
                ulonglong2 a23 = *(const ulonglong2*)&As[kk][ty * 8 + 4];
                // b: 8 pixels = 4 natural f32x2 pairs
                ulonglong2 b01 = *(const ulonglong2*)&Bs[kk][tx * 4];
                ulonglong2 b23 = *(const ulonglong2*)&Bs[kk][64 + tx * 4];

                FMA2(acc[0][0], a01.x, b01.x); FMA2(acc[0][1], a01.x, b01.y);
                FMA2(acc[0][2], a01.x, b23.x); FMA2(acc[0][3], a01.x, b23.y);
                FMA2(acc[1][0], a01.y, b01.x); FMA2(acc[1][1], a01.y, b01.y);
                FMA2(acc[1][2], a01.y, b23.x); FMA2(acc[1][3], a01.y, b23.y);
                FMA2(acc[2][0], a23.x, b01.x); FMA2(acc[2][1], a23.x, b01.y);
                FMA2(acc[2][2], a23.x, b23.x); FMA2(acc[2][3], a23.x, b23.y);
                FMA2(acc[3][0], a23.y, b01.x); FMA2(acc[3][1], a23.y, b01.y);
                FMA2(acc[3][2], a23.y, b23.x); FMA2(acc[3][3], a23.y, b23.y);
            }
            __syncthreads();
        }
    }

    // Epilogue: out[c] = E+O, out[255-c] = E-O
#pragma unroll
    for (int ci = 0; ci < 4; ++ci) {
        int c  = ctile * BM + ty * 4 + ci;   // [0,128)
        int cm = C_DIM - 1 - c;              // [128,256)

        float e0 = ULO(accE[ci][0]), e1 = UHI(accE[ci][0]);
        float e2 = ULO(accE[ci][1]), e3 = UHI(accE[ci][1]);
        float e4 = ULO(accE[ci][2]), e5 = UHI(accE[ci][2]);
        float e6 = ULO(accE[ci][3]), e7 = UHI(accE[ci][3]);
        float o0 = ULO(accO[ci][0]), o1 = UHI(accO[ci][0]);
        float o2 = ULO(accO[ci][1]), o3 = UHI(accO[ci][1]);
        float o4 = ULO(accO[ci][2]), o5 = UHI(accO[ci][2]);
        float o6 = ULO(accO[ci][3]), o7 = UHI(accO[ci][3]);

        float4 s1 = make_float4(e0 + o0, e1 + o1, e2 + o2, e3 + o3);
        float4 s2 = make_float4(e4 + o4, e5 + o5, e6 + o6, e7 + o7);
        float4 d1 = make_float4(e0 - o0, e1 - o1, e2 - o2, e3 - o3);
        float4 d2 = make_float4(e4 - o4, e5 - o5, e6 - o6, e7 - o7);

        *(float4*)&ob[(size_t)c * HW + tx * 4]        = s1;
        *(float4*)&ob[(size_t)c * HW + 64 + tx * 4]   = s2;
        *(float4*)&ob[(size_t)cm * HW + tx * 4]       = d1;
        *(float4*)&ob[(size_t)cm * HW + 64 + tx * 4]  = d2;
    }
}

extern "C" void kernel_launch(void* const* d_in, const int* in_sizes, int n_in,
                              void* d_out, int out_size) {
    const float* x = (const float*)d_in[0];
    float* out = (float*)d_out;

    int batches = in_sizes[0] / (C_DIM * HW);   // 8

    precompute_kernel<<<256, 128>>>();
    dim3 grid(HALF / BM, HW / BN, batches);     // (2, 128, 8)
    idct_gemm_kernel<<<grid, 256>>>(x, out);
}

// round 3
// speedup vs baseline: 2.4066x; 2.4066x over previous
#include <cuda_runtime.h>
#include <cuda_bf16.h>
#include <stdint.h>

// DCT-III along channels via mma.sync (bf16 3-term split, fp32 accum).
// out[b,c,p] = sum_k M[c,k] x[b,k,p],  M[c,k] = (k==0)?1:2*cos(pi*k*(2c+1)/512)
// Parity: E[c]=sum_{even k}, O[c]=sum_{odd k}; out[c]=E+O, out[255-c]=E-O.

#define C_DIM 256
#define HW    16384
#define THREADS 256

#define A_BYTES   131072            // [kt8][hl2][m256][16 bf16] = 128KB
#define B_OFF     131072            // [par2][hl2][n128][16 bf16] = 16KB
#define SMEM_TOTAL 147456
#define CS_STRIDE 136               // epilogue row stride in words (conflict-free)

// A image in fragment-natural layout: bf16 word (j,j+1) pairs per 32B row.
__device__ __align__(16) __nv_bfloat16 g_A[65536];

__global__ void precompute_kernel() {
    int t = blockIdx.x * blockDim.x + threadIdx.x;   // 32768 = (m, jg)
    int m = t >> 7;          // 0..255 (row: <128 = E rows c=m, >=128 = O rows)
    int jg = t & 127;        // reduced k index
    int c = m & 127;
    int p = m >> 7;
    int k = 2 * jg + p;
    float val;
    if (k == 0) val = 1.0f;
    else {
        int mm = (k * (2 * c + 1)) & 1023;           // exact integer phase mod 2
        val = 2.0f * cospif((float)mm * (1.0f / 512.0f));
    }
    __nv_bfloat16 hi = __float2bfloat16_rn(val);
    __nv_bfloat16 lo = __float2bfloat16_rn(val - __bfloat162float(hi));
    int kt = jg >> 4, jj = jg & 15;
    int idx = kt * 8192 + m * 16 + (jj >> 1) * 2 + (jj & 1);  // bf16 units
    g_A[idx] = hi;             // hl = 0
    g_A[idx + 4096] = lo;      // hl = 1
}

__device__ __forceinline__ void mma16816(float* c,
    uint32_t a0, uint32_t a1, uint32_t a2, uint32_t a3,
    uint32_t b0, uint32_t b1) {
    asm volatile(
        "mma.sync.aligned.m16n8k16.row.col.f32.bf16.bf16.f32 "
        "{%0,%1,%2,%3}, {%4,%5,%6,%7}, {%8,%9}, {%0,%1,%2,%3};"
        : "+f"(c[0]), "+f"(c[1]), "+f"(c[2]), "+f"(c[3])
        : "r"(a0), "r"(a1), "r"(a2), "r"(a3), "r"(b0), "r"(b1));
}

__global__ __launch_bounds__(THREADS, 1)
void idct_mma_kernel(const float* __restrict__ x, float* __restrict__ out) {
    extern __shared__ char sm[];
    const int tid = threadIdx.x;
    const int lane = tid & 31;
    const int wid = tid >> 5;
    const int mhalf = wid & 1;     // 0: E rows (m 0..127), 1: O rows (m 128..255)
    const int wpx = wid >> 1;      // 32-px group
    const int ptile = blockIdx.x;
    const int batch = blockIdx.y;

    const float* xb = x + (size_t)batch * C_DIM * HW + (size_t)ptile * 128;
    float* ob = out + (size_t)batch * C_DIM * HW + (size_t)ptile * 128;

    // ---- stage A (128KB) from gmem (L2-hot) into smem, layout identical ----
    {
        const uint4* src = (const uint4*)g_A;
        uint4* dst = (uint4*)sm;
#pragma unroll
        for (int i = 0; i < 32; ++i) dst[tid + 256 * i] = src[tid + 256 * i];
    }

    float acc[8][4][4];
#pragma unroll
    for (int a = 0; a < 8; a++)
#pragma unroll
        for (int b = 0; b < 4; b++)
#pragma unroll
            for (int cc = 0; cc < 4; cc++) acc[a][b][cc] = 0.0f;

    // ---- B producer indices: thread handles (parity g, pixel px), 16 j's ----
    const int px = tid & 127;
    const int g = tid >> 7;
    const float* xk = xb + (size_t)g * HW + px;

    float v[16];
#pragma unroll
    for (int i = 0; i < 16; ++i) v[i] = xk[(size_t)(2 * i) * HW];

    const int frow = lane >> 2;          // fragment row group
    const int fcol4 = (lane & 3) * 4;    // fragment k-pair byte offset

#pragma unroll 1
    for (int kt = 0; kt < 8; ++kt) {
        // convert v -> bf16 hi/lo packed words
        uint4 h0, h1, l0, l1;
        {
            uint32_t hw_[8], lw_[8];
#pragma unroll
            for (int w = 0; w < 8; ++w) {
                __nv_bfloat162 h2 = __floats2bfloat162_rn(v[2 * w], v[2 * w + 1]);
                float2 hf = __bfloat1622float2(h2);
                __nv_bfloat162 l2 =
                    __floats2bfloat162_rn(v[2 * w] - hf.x, v[2 * w + 1] - hf.y);
                hw_[w] = *(uint32_t*)&h2;
                lw_[w] = *(uint32_t*)&l2;
            }
            h0 = make_uint4(hw_[0], hw_[1], hw_[2], hw_[3]);
            h1 = make_uint4(hw_[4], hw_[5], hw_[6], hw_[7]);
            l0 = make_uint4(lw_[0], lw_[1], lw_[2], lw_[3]);
            l1 = make_uint4(lw_[4], lw_[5], lw_[6], lw_[7]);
        }
        if (kt > 0) __syncthreads();     // prior mma done reading B
        {
            char* bp = sm + B_OFF + g * 8192 + px * 32;
            *(uint4*)(bp) = h0;
            *(uint4*)(bp + 16) = h1;
            *(uint4*)(bp + 4096) = l0;
            *(uint4*)(bp + 4096 + 16) = l1;
        }
        if (kt < 7) {                    // issue next loads early (latency hidden by mma)
            const float* xn = xk + (size_t)(32 * (kt + 1)) * HW;
#pragma unroll
            for (int i = 0; i < 16; ++i) v[i] = xn[(size_t)(2 * i) * HW];
        }
        __syncthreads();                 // B visible

        // ---- fragment loads (all plain conflict-free LDS.32) ----
        uint32_t Bh[4][2], Bl[4][2];
#pragma unroll
        for (int nt = 0; nt < 4; ++nt) {
            const char* bb = sm + B_OFF + mhalf * 8192 +
                             (wpx * 32 + nt * 8 + frow) * 32 + fcol4;
            Bh[nt][0] = *(const uint32_t*)(bb);
            Bh[nt][1] = *(const uint32_t*)(bb + 16);
            Bl[nt][0] = *(const uint32_t*)(bb + 4096);
            Bl[nt][1] = *(const uint32_t*)(bb + 4096 + 16);
        }
        uint32_t Af[8][4];
        const char* ab0 = sm + kt * 16384 + (mhalf * 128 + frow) * 32 + fcol4;
#pragma unroll
        for (int mt = 0; mt < 8; ++mt) {
            const char* ab = ab0 + mt * 512;     // 16 rows * 32B
            Af[mt][0] = *(const uint32_t*)(ab);
            Af[mt][1] = *(const uint32_t*)(ab + 256);
            Af[mt][2] = *(const uint32_t*)(ab + 16);
            Af[mt][3] = *(const uint32_t*)(ab + 272);
        }
        // Ah*Bh and Ah*Bl
#pragma unroll
        for (int mt = 0; mt < 8; ++mt)
#pragma unroll
            for (int nt = 0; nt < 4; ++nt)
                mma16816(acc[mt][nt], Af[mt][0], Af[mt][1], Af[mt][2], Af[mt][3],
                         Bh[nt][0], Bh[nt][1]);
#pragma unroll
        for (int mt = 0; mt < 8; ++mt)
#pragma unroll
            for (int nt = 0; nt < 4; ++nt)
                mma16816(acc[mt][nt], Af[mt][0], Af[mt][1], Af[mt][2], Af[mt][3],
                         Bl[nt][0], Bl[nt][1]);
        // Al*Bh
#pragma unroll
        for (int mt = 0; mt < 8; ++mt) {
            const char* ab = ab0 + 8192 + mt * 512;
            Af[mt][0] = *(const uint32_t*)(ab);
            Af[mt][1] = *(const uint32_t*)(ab + 256);
            Af[mt][2] = *(const uint32_t*)(ab + 16);
            Af[mt][3] = *(const uint32_t*)(ab + 272);
        }
#pragma unroll
        for (int mt = 0; mt < 8; ++mt)
#pragma unroll
            for (int nt = 0; nt < 4; ++nt)
                mma16816(acc[mt][nt], Af[mt][0], Af[mt][1], Af[mt][2], Af[mt][3],
                         Bh[nt][0], Bh[nt][1]);
    }

    // ---- epilogue: frags -> padded smem -> parity combine -> coalesced STG ----
    __syncthreads();                     // all mma done; reuse A region
    float* Cs = (float*)sm;
#pragma unroll
    for (int mt = 0; mt < 8; ++mt)
#pragma unroll
        for (int nt = 0; nt < 4; ++nt) {
            int m = mhalf * 128 + mt * 16 + frow;
            int n = wpx * 32 + nt * 8 + (lane & 3) * 2;
            *(float2*)&Cs[m * CS_STRIDE + n] =
                make_float2(acc[mt][nt][0], acc[mt][nt][1]);
            *(float2*)&Cs[(m + 8) * CS_STRIDE + n] =
                make_float2(acc[mt][nt][2], acc[mt][nt][3]);
        }
    __syncthreads();

#pragma unroll
    for (int i = 0; i < 16; ++i) {
        int cc = wid * 16 + i;           // 0..127
        float4 e = *(float4*)&Cs[cc * CS_STRIDE + lane * 4];
        float4 o = *(float4*)&Cs[(128 + cc) * CS_STRIDE + lane * 4];
        float4 s = make_float4(e.x + o.x, e.y + o.y, e.z + o.z, e.w + o.w);
        float4 d = make_float4(e.x - o.x, e.y - o.y, e.z - o.z, e.w - o.w);
        *(float4*)&ob[(size_t)cc * HW + lane * 4] = s;
        *(float4*)&ob[(size_t)(255 - cc) * HW + lane * 4] = d;
    }
}

extern "C" void kernel_launch(void* const* d_in, const int* in_sizes, int n_in,
                              void* d_out, int out_size) {
    const float* x = (const float*)d_in[0];
    float* out = (float*)d_out;
    int batches = in_sizes[0] / (C_DIM * HW);   // 8

    cudaFuncSetAttribute(idct_mma_kernel,
                         cudaFuncAttributeMaxDynamicSharedMemorySize, SMEM_TOTAL);
    precompute_kernel<<<128, 256>>>();
    dim3 grid(HW / 128, batches);               // (128, 8)
    idct_mma_kernel<<<grid, THREADS, SMEM_TOTAL>>>(x, out);
}

// round 5
// speedup vs baseline: 3.1715x; 1.3178x over previous
#include <cuda_runtime.h>
#include <cuda_bf16.h>
#include <stdint.h>

// DCT-III along channels via mma.sync m16n8k16 (bf16 3-term split, fp32 accum).
// out[b,c,p] = sum_k M[c,k] x[b,k,p],  M[c,k] = (k==0)?1:2*cos(pi*k*(2c+1)/512)
// Parity: E[c]=sum_{even k}, O[c]=sum_{odd k}; out[c]=E+O, out[255-c]=E-O.
// Persistent CTAs: A (128KB, swizzled fragment layout) staged in smem once.

#define C_DIM  256
#define HW     16384
#define NTILES 1024
#define GRID_P 148
#define THREADS 256

#define B_OFF  131072
#define SMEM_TOTAL 163840   // A 128KB + B double-buffer 32KB

// A image: [kt8][hl2][m256][32B row], 16B chunks xor-swizzled by (m&4)<<2
__device__ __align__(16) unsigned char g_A[131072];

__global__ void precompute_kernel() {
    int t = blockIdx.x * blockDim.x + threadIdx.x;   // 32768 = (m, jg)
    int m = t >> 7;          // row: <128 E (k even), >=128 O (k odd)
    int jg = t & 127;        // reduced k index
    int c = m & 127, p = m >> 7;
    int k = 2 * jg + p;
    float val;
    if (k == 0) val = 1.0f;
    else {
        int mm = (k * (2 * c + 1)) & 1023;           // exact integer phase
        val = 2.0f * cospif((float)mm * (1.0f / 512.0f));
    }
    __nv_bfloat16 hi = __float2bfloat16_rn(val);
    __nv_bfloat16 lo = __float2bfloat16_rn(val - __bfloat162float(hi));
    int kt = jg >> 4, jj = jg & 15;
    int w = jj >> 1, b = jj & 1;
    int off = kt * 16384 + m * 32 + (((w >> 2) << 4) ^ ((m & 4) << 2)) + (w & 3) * 4 + b * 2;
    *(__nv_bfloat16*)(g_A + off) = hi;                // hl=0
    *(__nv_bfloat16*)(g_A + off + 8192) = lo;         // hl=1
}

__device__ __forceinline__ void mma16816(float* c,
    uint32_t a0, uint32_t a1, uint32_t a2, uint32_t a3,
    uint32_t b0, uint32_t b1) {
    asm volatile(
        "mma.sync.aligned.m16n8k16.row.col.f32.bf16.bf16.f32 "
        "{%0,%1,%2,%3}, {%4,%5,%6,%7}, {%8,%9}, {%0,%1,%2,%3};"
        : "+f"(c[0]), "+f"(c[1]), "+f"(c[2]), "+f"(c[3])
        : "r"(a0), "r"(a1), "r"(a2), "r"(a3), "r"(b0), "r"(b1));
}

__global__ __launch_bounds__(THREADS, 1)
void idct_mma_kernel(const float* __restrict__ x, float* __restrict__ out) {
    extern __shared__ char sm[];
    const int tid  = threadIdx.x;
    const int lane = tid & 31;
    const int q    = lane & 3;
    const int frow = lane >> 2;
    const int wid  = tid >> 5;
    const int cg   = wid & 1;    // c group (64 channels)
    const int pg   = wid >> 1;   // px group (32 pixels)

    // B producer role
    const int px  = tid & 127;
    const int par = tid >> 7;

    // fragment address constants
    const uint32_t axor  = (uint32_t)((frow & 4) << 2);
    const uint32_t c0off = (0u ^ axor) + q * 4;
    const uint32_t c1off = (16u ^ axor) + q * 4;
    const uint32_t sxor  = (uint32_t)((px & 4) << 2);
    const uint32_t sbase = B_OFF + par * 8192 + px * 32;

    int ti = blockIdx.x;

    // prefetch v for first tile (k rows = kt0: 2i+par)
    const float* xpb = x + (size_t)(ti >> 7) * C_DIM * HW + (ti & 127) * 128
                         + (size_t)par * HW + px;
    float v[16];
#pragma unroll
    for (int i = 0; i < 16; ++i) v[i] = xpb[(size_t)(2 * i) * HW];

    // stage A once (128KB)
    {
        const uint4* src = (const uint4*)g_A;
        uint4* dst = (uint4*)sm;
#pragma unroll
        for (int i = 0; i < 32; ++i) dst[tid + 256 * i] = src[tid + 256 * i];
    }

    float acc[4][2][4][4];
#pragma unroll
    for (int a = 0; a < 4; a++)
#pragma unroll
        for (int e = 0; e < 2; e++)
#pragma unroll
            for (int b = 0; b < 4; b++)
#pragma unroll
                for (int j = 0; j < 4; j++) acc[a][e][b][j] = 0.0f;

    while (ti < NTILES) {
        const float* xnb = xpb;    // next-tile base (set at kt==7)

#pragma unroll 1
        for (int kt = 0; kt < 8; ++kt) {
            const uint32_t bufo = B_OFF + (uint32_t)(kt & 1) * 16384;

            // convert v -> bf16 hi/lo packed words
            uint32_t hw_[8], lw_[8];
#pragma unroll
            for (int w = 0; w < 8; ++w) {
                __nv_bfloat162 h2 = __floats2bfloat162_rn(v[2 * w], v[2 * w + 1]);
                float2 hf = __bfloat1622float2(h2);
                __nv_bfloat162 l2 =
                    __floats2bfloat162_rn(v[2 * w] - hf.x, v[2 * w + 1] - hf.y);
                hw_[w] = *(uint32_t*)&h2;
                lw_[w] = *(uint32_t*)&l2;
            }
            {
                char* bp = sm + (bufo - B_OFF) + sbase;
                *(uint4*)(bp + (0u ^ sxor)) = make_uint4(hw_[0], hw_[1], hw_[2], hw_[3]);
                *(uint4*)(bp + (16u ^ sxor)) = make_uint4(hw_[4], hw_[5], hw_[6], hw_[7]);
                *(uint4*)(bp + 4096 + (0u ^ sxor)) = make_uint4(lw_[0], lw_[1], lw_[2], lw_[3]);
                *(uint4*)(bp + 4096 + (16u ^ sxor)) = make_uint4(lw_[4], lw_[5], lw_[6], lw_[7]);
            }

            // prefetch next k chunk (or next tile's kt0)
            const float* nb;
            if (kt < 7) {
                nb = xpb + (size_t)(32 * (kt + 1)) * HW;
            } else {
                int tn = (ti + GRID_P < NTILES) ? (ti + GRID_P) : ti;
                nb = x + (size_t)(tn >> 7) * C_DIM * HW + (tn & 127) * 128
                       + (size_t)par * HW + px;
                xnb = nb;
            }
#pragma unroll
            for (int i = 0; i < 16; ++i) v[i] = nb[(size_t)(2 * i) * HW];

            __syncthreads();

            // ---- B fragments: [par][nt][hl][word], conflict-free LDS.32 ----
            uint32_t Bf[2][4][2][2];
#pragma unroll
            for (int pr = 0; pr < 2; ++pr)
#pragma unroll
                for (int nt = 0; nt < 4; ++nt) {
                    const char* bb = sm + (bufo - B_OFF) + B_OFF + pr * 8192 +
                                     (pg * 32 + nt * 8 + frow) * 32;
                    Bf[pr][nt][0][0] = *(const uint32_t*)(bb + c0off);
                    Bf[pr][nt][0][1] = *(const uint32_t*)(bb + c1off);
                    Bf[pr][nt][1][0] = *(const uint32_t*)(bb + 4096 + c0off);
                    Bf[pr][nt][1][1] = *(const uint32_t*)(bb + 4096 + c1off);
                }

            // ---- A tiles (4 mt x 2 parities) + mma ----
#pragma unroll
            for (int eo = 0; eo < 2; ++eo)
#pragma unroll
                for (int mt = 0; mt < 4; ++mt) {
                    const char* ab = sm + kt * 16384 +
                                     (eo * 128 + cg * 64 + mt * 16 + frow) * 32;
                    uint32_t ah0 = *(const uint32_t*)(ab + c0off);
                    uint32_t ah1 = *(const uint32_t*)(ab + 256 + c0off);
                    uint32_t ah2 = *(const uint32_t*)(ab + c1off);
                    uint32_t ah3 = *(const uint32_t*)(ab + 256 + c1off);
                    uint32_t al0 = *(const uint32_t*)(ab + 8192 + c0off);
                    uint32_t al1 = *(const uint32_t*)(ab + 8448 + c0off);
                    uint32_t al2 = *(const uint32_t*)(ab + 8192 + c1off);
                    uint32_t al3 = *(const uint32_t*)(ab + 8448 + c1off);
#pragma unroll
                    for (int nt = 0; nt < 4; ++nt) {
                        mma16816(acc[mt][eo][nt], ah0, ah1, ah2, ah3,
                                 Bf[eo][nt][0][0], Bf[eo][nt][0][1]);
                        mma16816(acc[mt][eo][nt], ah0, ah1, ah2, ah3,
                                 Bf[eo][nt][1][0], Bf[eo][nt][1][1]);
                        mma16816(acc[mt][eo][nt], al0, al1, al2, al3,
                                 Bf[eo][nt][0][0], Bf[eo][nt][0][1]);
                    }
                }
        }

        // ---- epilogue: parity combine in regs, direct sector-aligned STG ----
        {
            float* ob = out + (size_t)(ti >> 7) * C_DIM * HW + (ti & 127) * 128;
#pragma unroll
            for (int mt = 0; mt < 4; ++mt) {
                int c = cg * 64 + mt * 16 + frow;
#pragma unroll
                for (int nt = 0; nt < 4; ++nt) {
                    int pxo = pg * 32 + nt * 8 + q * 2;
                    float* E = acc[mt][0][nt];
                    float* O = acc[mt][1][nt];
                    *(float2*)&ob[(size_t)c * HW + pxo] =
                        make_float2(E[0] + O[0], E[1] + O[1]);
                    *(float2*)&ob[(size_t)(255 - c) * HW + pxo] =
                        make_float2(E[0] - O[0], E[1] - O[1]);
                    *(float2*)&ob[(size_t)(c + 8) * HW + pxo] =
                        make_float2(E[2] + O[2], E[3] + O[3]);
                    *(float2*)&ob[(size_t)(247 - c) * HW + pxo] =
                        make_float2(E[2] - O[2], E[3] - O[3]);
                    E[0] = E[1] = E[2] = E[3] = 0.0f;
                    O[0] = O[1] = O[2] = O[3] = 0.0f;
                }
            }
        }

        ti += GRID_P;
        xpb = xnb;
    }
}

extern "C" void kernel_launch(void* const* d_in, const int* in_sizes, int n_in,
                              void* d_out, int out_size) {
    const float* x = (const float*)d_in[0];
    float* out = (float*)d_out;

    cudaFuncSetAttribute(idct_mma_kernel,
                         cudaFuncAttributeMaxDynamicSharedMemorySize, SMEM_TOTAL);
    precompute_kernel<<<128, 256>>>();
    idct_mma_kernel<<<GRID_P, THREADS, SMEM_TOTAL>>>(x, out);
}

// round 6
// speedup vs baseline: 3.7119x; 1.1704x over previous
#include <cuda_runtime.h>
#include <cuda_fp16.h>
#include <stdint.h>

// DCT-III along channels via mma.sync m16n8k16 fp16 (A single, B hi/lo split).
// out[b,c,p] = sum_k M[c,k] x[b,k,p],  M[c,k] = (k==0)?1:2*cos(pi*k*(2c+1)/512)
// Parity: E[c]=sum_{even k}, O[c]=sum_{odd k}; out[c]=E+O, out[255-c]=E-O.
// D = A_fp16*(Bh + Bl): 2 mma passes; A error ~2^-12 rel -> rel_err ~1.5e-4.
// Persistent CTAs; A (64KB, fragment-lane-major) staged in smem once.

#define C_DIM  256
#define HW     16384
#define NTILES 1024
#define GRID_P 148
#define THREADS 256

#define SMB 65536
#define SMEM_TOTAL 98304   // A 64KB + B double buffer 2x16KB

// A image: [kt8][t16 16][lane 32][16B] ; t16 = eo*8 + cg*4 + mt
__device__ __align__(16) unsigned char g_A[65536];

__global__ void precompute_kernel() {
    int t = blockIdx.x * blockDim.x + threadIdx.x;   // 4096 = [kt][t16][lane]
    int kt = t >> 9;
    int t16 = (t >> 5) & 15;
    int lane = t & 31;
    int gid = lane >> 2, tig = lane & 3;
    int eo = t16 >> 3;
    uint32_t w4[4];
#pragma unroll
    for (int w = 0; w < 4; ++w) {
        int m = t16 * 16 + gid + (w & 1) * 8;
        int c = m & 127;
        int kap0 = tig * 2 + (w >> 1) * 8;
        float v2[2];
#pragma unroll
        for (int h = 0; h < 2; ++h) {
            int k = kt * 32 + 2 * (kap0 + h) + eo;
            if (k == 0) v2[h] = 1.0f;
            else {
                int mm = (k * (2 * c + 1)) & 1023;
                v2[h] = 2.0f * cospif((float)mm * (1.0f / 512.0f));
            }
        }
        __half2 h2 = __floats2half2_rn(v2[0], v2[1]);
        w4[w] = *(uint32_t*)&h2;
    }
    *(uint4*)(g_A + (kt * 16 + t16) * 512 + lane * 16) =
        make_uint4(w4[0], w4[1], w4[2], w4[3]);
}

__device__ __forceinline__ void mma16816(float* c,
    uint32_t a0, uint32_t a1, uint32_t a2, uint32_t a3,
    uint32_t b0, uint32_t b1) {
    asm volatile(
        "mma.sync.aligned.m16n8k16.row.col.f32.f16.f16.f32 "
        "{%0,%1,%2,%3}, {%4,%5,%6,%7}, {%8,%9}, {%0,%1,%2,%3};"
        : "+f"(c[0]), "+f"(c[1]), "+f"(c[2]), "+f"(c[3])
        : "r"(a0), "r"(a1), "r"(a2), "r"(a3), "r"(b0), "r"(b1));
}

__global__ __launch_bounds__(THREADS, 1)
void idct_mma_kernel(const float* __restrict__ x, float* __restrict__ out) {
    extern __shared__ char sm[];
    const int tid  = threadIdx.x;
    const int lane = tid & 31;
    const int q    = lane & 3;
    const int frow = lane >> 2;
    const int wid  = tid >> 5;
    const int cg   = wid & 1;    // c group (64 channels)
    const int pg   = wid >> 1;   // px group (32 pixels)

    // B producer role
    const int px  = tid & 127;
    const int par = tid >> 7;
    const int g8  = px >> 3;
    const int r   = px & 7;
    const uint32_t psw = (uint32_t)((r & 4) << 2);
    const uint32_t po1 = (uint32_t)(par * 8192 + g8 * 512) + (((uint32_t)(r * 32)) ^ psw);
    const uint32_t po2 = (uint32_t)(par * 8192 + g8 * 512) + (((uint32_t)(r * 32 + 16)) ^ psw);
    // B consumer offset
    const uint32_t bco = (((uint32_t)(frow * 32 + q * 8)) ^ ((uint32_t)((frow & 4) << 2)));

    int ti = blockIdx.x;

    const float* xpb = x + (size_t)(ti >> 7) * C_DIM * HW + (ti & 127) * 128
                         + (size_t)par * HW + px;
    float v[16];
#pragma unroll
    for (int i = 0; i < 16; ++i) v[i] = xpb[(size_t)(2 * i) * HW];

    // stage A once (64KB)
    {
        const uint4* src = (const uint4*)g_A;
        uint4* dst = (uint4*)sm;
#pragma unroll
        for (int i = 0; i < 16; ++i) dst[tid + 256 * i] = src[tid + 256 * i];
    }

    float acc[4][2][4][4];
#pragma unroll
    for (int a = 0; a < 4; a++)
#pragma unroll
        for (int e = 0; e < 2; e++)
#pragma unroll
            for (int b = 0; b < 4; b++)
#pragma unroll
                for (int j = 0; j < 4; j++) acc[a][e][b][j] = 0.0f;

    while (ti < NTILES) {
        const float* xnb = xpb;

#pragma unroll 1
        for (int kt = 0; kt < 8; ++kt) {
            const uint32_t buf = (uint32_t)(kt & 1) * 16384;

            // convert v -> fp16 hi + fp16 lo, fragment word order
            // word w pairs: {(0,1),(8,9),(2,3),(10,11),(4,5),(12,13),(6,7),(14,15)}
            uint32_t hw_[8], lw_[8];
            const int Wa[8] = {0, 8, 2, 10, 4, 12, 6, 14};
#pragma unroll
            for (int w = 0; w < 8; ++w) {
                int a = Wa[w];
                __half2 h2 = __floats2half2_rn(v[a], v[a + 1]);
                float2 hf = __half22float2(h2);
                __half2 l2 = __floats2half2_rn(v[a] - hf.x, v[a + 1] - hf.y);
                hw_[w] = *(uint32_t*)&h2;
                lw_[w] = *(uint32_t*)&l2;
            }
            {
                char* bb = sm + SMB + buf;
                *(uint4*)(bb + po1) = make_uint4(hw_[0], hw_[1], hw_[2], hw_[3]);
                *(uint4*)(bb + po2) = make_uint4(hw_[4], hw_[5], hw_[6], hw_[7]);
                *(uint4*)(bb + 256 + po1) = make_uint4(lw_[0], lw_[1], lw_[2], lw_[3]);
                *(uint4*)(bb + 256 + po2) = make_uint4(lw_[4], lw_[5], lw_[6], lw_[7]);
            }

            // prefetch next k chunk (or next tile's kt0)
            const float* nb;
            if (kt < 7) {
                nb = xpb + (size_t)(32 * (kt + 1)) * HW;
            } else {
                int tn = (ti + GRID_P < NTILES) ? (ti + GRID_P) : ti;
                nb = x + (size_t)(tn >> 7) * C_DIM * HW + (tn & 127) * 128
                       + (size_t)par * HW + px;
                xnb = nb;
            }
#pragma unroll
            for (int i = 0; i < 16; ++i) v[i] = nb[(size_t)(2 * i) * HW];

            __syncthreads();

            // ---- B fragments: LDS.64, conflict-free ----
            uint2 Bh[2][4], Bl[2][4];
#pragma unroll
            for (int pr = 0; pr < 2; ++pr)
#pragma unroll
                for (int nt = 0; nt < 4; ++nt) {
                    const char* bb = sm + SMB + buf + pr * 8192 +
                                     (pg * 4 + nt) * 512 + bco;
                    Bh[pr][nt] = *(const uint2*)(bb);
                    Bl[pr][nt] = *(const uint2*)(bb + 256);
                }

            // ---- A fragments: one LDS.128 per m16 tile; 2 mma per (eo,mt,nt) ----
#pragma unroll
            for (int eo = 0; eo < 2; ++eo)
#pragma unroll
                for (int mt = 0; mt < 4; ++mt) {
                    uint4 Aw = *(const uint4*)(sm +
                        (kt * 16 + eo * 8 + cg * 4 + mt) * 512 + lane * 16);
#pragma unroll
                    for (int nt = 0; nt < 4; ++nt) {
                        mma16816(acc[mt][eo][nt], Aw.x, Aw.y, Aw.z, Aw.w,
                                 Bh[eo][nt].x, Bh[eo][nt].y);
                        mma16816(acc[mt][eo][nt], Aw.x, Aw.y, Aw.z, Aw.w,
                                 Bl[eo][nt].x, Bl[eo][nt].y);
                    }
                }
        }

        // ---- epilogue: parity combine in regs, direct sector-aligned STG ----
        {
            float* ob = out + (size_t)(ti >> 7) * C_DIM * HW + (ti & 127) * 128;
#pragma unroll
            for (int mt = 0; mt < 4; ++mt) {
                int c = cg * 64 + mt * 16 + frow;
#pragma unroll
                for (int nt = 0; nt < 4; ++nt) {
                    int pxo = pg * 32 + nt * 8 + q * 2;
                    float* E = acc[mt][0][nt];
                    float* O = acc[mt][1][nt];
                    *(float2*)&ob[(size_t)c * HW + pxo] =
                        make_float2(E[0] + O[0], E[1] + O[1]);
                    *(float2*)&ob[(size_t)(255 - c) * HW + pxo] =
                        make_float2(E[0] - O[0], E[1] - O[1]);
                    *(float2*)&ob[(size_t)(c + 8) * HW + pxo] =
                        make_float2(E[2] + O[2], E[3] + O[3]);
                    *(float2*)&ob[(size_t)(247 - c) * HW + pxo] =
                        make_float2(E[2] - O[2], E[3] - O[3]);
                    E[0] = E[1] = E[2] = E[3] = 0.0f;
                    O[0] = O[1] = O[2] = O[3] = 0.0f;
                }
            }
        }

        ti += GRID_P;
        xpb = xnb;
    }
}

extern "C" void kernel_launch(void* const* d_in, const int* in_sizes, int n_in,
                              void* d_out, int out_size) {
    const float* x = (const float*)d_in[0];
    float* out = (float*)d_out;

    cudaFuncSetAttribute(idct_mma_kernel,
                         cudaFuncAttributeMaxDynamicSharedMemorySize, SMEM_TOTAL);
    precompute_kernel<<<16, 256>>>();
    idct_mma_kernel<<<GRID_P, THREADS, SMEM_TOTAL>>>(x, out);
}